// round 8
// baseline (speedup 1.0000x reference)
#include <cuda_runtime.h>
#include <cstdint>

#define N_NODES 100000
#define N_EDGES 1600000
#define DIM     128
#define SCAN_BS 1024
#define NSCAN   ((N_NODES + SCAN_BS - 1) / SCAN_BS)   // 98

// Scratch (no cudaMalloc allowed)
__device__ int   g_deg[N_NODES];
__device__ float g_norm[N_NODES];
__device__ int   g_part[N_NODES];
__device__ int   g_bsum[NSCAN];
__device__ int   g_row_start[N_NODES + 1];
__device__ int   g_cursor[N_NODES];
__device__ int   g_sorted_src[N_EDGES];

// ---------------------------------------------------------------------------
// 1. zero degree counters
// ---------------------------------------------------------------------------
__global__ void zero_deg_kernel() {
    int i = blockIdx.x * blockDim.x + threadIdx.x;
    if (i < N_NODES) g_deg[i] = 0;
}

// ---------------------------------------------------------------------------
// 2. in-degree histogram
// ---------------------------------------------------------------------------
__global__ void deg_kernel(const int* __restrict__ edge_dst) {
    int i = blockIdx.x * blockDim.x + threadIdx.x;
    if (i < N_EDGES) atomicAdd(&g_deg[edge_dst[i]], 1);
}

// ---------------------------------------------------------------------------
// 3a. per-block exclusive scan of deg
// ---------------------------------------------------------------------------
__global__ __launch_bounds__(SCAN_BS)
void scan_block_kernel() {
    __shared__ int s[SCAN_BS];
    int tid = threadIdx.x;
    int gi  = blockIdx.x * SCAN_BS + tid;
    int v = (gi < N_NODES) ? g_deg[gi] : 0;
    s[tid] = v;
    __syncthreads();
#pragma unroll
    for (int off = 1; off < SCAN_BS; off <<= 1) {
        int t = (tid >= off) ? s[tid - off] : 0;
        __syncthreads();
        s[tid] += t;
        __syncthreads();
    }
    if (gi < N_NODES) g_part[gi] = s[tid] - v;
    if (tid == SCAN_BS - 1) g_bsum[blockIdx.x] = s[tid];
}

// ---------------------------------------------------------------------------
// 3b. finalize: re-scan the 98 block sums locally, build row_start/cursor/norm
// ---------------------------------------------------------------------------
__global__ __launch_bounds__(256)
void finalize_kernel() {
    __shared__ int ss[128];
    int tid = threadIdx.x;
    if (tid < 128) ss[tid] = (tid < NSCAN) ? g_bsum[tid] : 0;
    __syncthreads();
#pragma unroll
    for (int off = 1; off < 128; off <<= 1) {
        int t = (tid < 128 && tid >= off) ? ss[tid - off] : 0;
        __syncthreads();
        if (tid < 128) ss[tid] += t;
        __syncthreads();
    }
    int i = blockIdx.x * blockDim.x + tid;
    if (i < N_NODES) {
        int reg = i / SCAN_BS;
        int boff = (reg == 0) ? 0 : ss[reg - 1];
        int rs = g_part[i] + boff;
        g_row_start[i] = rs;
        g_cursor[i]    = rs;
        int d = g_deg[i];
        g_norm[i] = rsqrtf((float)(d > 0 ? d : 1));
    }
    if (i == 0) g_row_start[N_NODES] = N_EDGES;
}

// ---------------------------------------------------------------------------
// 4. bucket edges by dst
// ---------------------------------------------------------------------------
__global__ void csr_scatter_kernel(const int* __restrict__ edge_src,
                                   const int* __restrict__ edge_dst) {
    int e = blockIdx.x * blockDim.x + threadIdx.x;
    if (e < N_EDGES) {
        int d = edge_dst[e];
        int pos = atomicAdd(&g_cursor[d], 1);
        g_sorted_src[pos] = edge_src[e];
    }
}

// ---------------------------------------------------------------------------
// 5. FUSED gather + tf32 MMA GEMM
//    Block = 128 node-rows, 512 threads (16 warps), 1 block/SM (135KB smem).
//    Phase 1: stage W[128][128] -> sW tf32.
//    Phase 2: warp w gathers rows {w, w+16, ...} -> sA tf32 (norm-scaled).
//    Phase 3: mma.sync m16n8k8, warps 4m x 4n, warp tile 32x32.
// ---------------------------------------------------------------------------
#define SW_STRIDE 132
#define SA_STRIDE 132
#define SMEM_W_WORDS (128 * SW_STRIDE)
#define SMEM_A_WORDS (128 * SA_STRIDE)
#define SMEM_SZ ((SMEM_W_WORDS + SMEM_A_WORDS) * 4)   // 135168 B

__device__ __forceinline__ uint32_t f2tf32(float f) {
    uint32_t r;
    asm("cvt.rna.tf32.f32 %0, %1;" : "=r"(r) : "f"(f));
    return r;
}

__global__ __launch_bounds__(512)
void fused_gather_gemm_kernel(const float* __restrict__ h,
                              const float* __restrict__ W,
                              const float* __restrict__ bias,
                              float*       __restrict__ out) {
    extern __shared__ uint32_t sm[];
    uint32_t* sW = sm;                  // [n][k] tf32
    uint32_t* sA = sm + SMEM_W_WORDS;   // [m][k] tf32

    int tid  = threadIdx.x;
    int lane = tid & 31;
    int warp = tid >> 5;     // 0..15
    int row0 = blockIdx.x * 128;

    // ---- Phase 1: stage W as tf32 ----
    {
        const float4* W4 = (const float4*)W;
#pragma unroll
        for (int t = tid; t < 4096; t += 512) {
            int n = t >> 5;
            int q = t & 31;
            float4 w = __ldg(&W4[n * 32 + q]);
            uint32_t* p = &sW[n * SW_STRIDE + q * 4];
            p[0] = f2tf32(w.x); p[1] = f2tf32(w.y);
            p[2] = f2tf32(w.z); p[3] = f2tf32(w.w);
        }
    }

    // ---- Phase 2: gather 8 rows per warp, write sA as tf32 ----
    {
        const float4* h4 = (const float4*)h;
#pragma unroll
        for (int rr = 0; rr < 8; rr++) {
            int r   = warp + rr * 16;      // 0..127
            int row = row0 + r;
            float4 acc = make_float4(0.f, 0.f, 0.f, 0.f);
            if (row < N_NODES) {
                int st = __ldg(&g_row_start[row]);
                int en = __ldg(&g_row_start[row + 1]);
                int e = st;
                for (; e + 3 < en; e += 4) {
                    int s0 = __ldg(&g_sorted_src[e]);
                    int s1 = __ldg(&g_sorted_src[e + 1]);
                    int s2 = __ldg(&g_sorted_src[e + 2]);
                    int s3 = __ldg(&g_sorted_src[e + 3]);
                    float n0 = __ldg(&g_norm[s0]);
                    float n1 = __ldg(&g_norm[s1]);
                    float n2 = __ldg(&g_norm[s2]);
                    float n3 = __ldg(&g_norm[s3]);
                    float4 v0 = __ldg(&h4[(size_t)s0 * 32 + lane]);
                    float4 v1 = __ldg(&h4[(size_t)s1 * 32 + lane]);
                    float4 v2 = __ldg(&h4[(size_t)s2 * 32 + lane]);
                    float4 v3 = __ldg(&h4[(size_t)s3 * 32 + lane]);
                    acc.x += v0.x * n0 + v1.x * n1 + v2.x * n2 + v3.x * n3;
                    acc.y += v0.y * n0 + v1.y * n1 + v2.y * n2 + v3.y * n3;
                    acc.z += v0.z * n0 + v1.z * n1 + v2.z * n2 + v3.z * n3;
                    acc.w += v0.w * n0 + v1.w * n1 + v2.w * n2 + v3.w * n3;
                }
                for (; e < en; e++) {
                    int s0 = __ldg(&g_sorted_src[e]);
                    float n0 = __ldg(&g_norm[s0]);
                    float4 v0 = __ldg(&h4[(size_t)s0 * 32 + lane]);
                    acc.x += v0.x * n0; acc.y += v0.y * n0;
                    acc.z += v0.z * n0; acc.w += v0.w * n0;
                }
                float nd = __ldg(&g_norm[row]);
                acc.x *= nd; acc.y *= nd; acc.z *= nd; acc.w *= nd;
            }
            uint32_t* p = &sA[r * SA_STRIDE + lane * 4];
            p[0] = f2tf32(acc.x); p[1] = f2tf32(acc.y);
            p[2] = f2tf32(acc.z); p[3] = f2tf32(acc.w);
        }
    }
    __syncthreads();

    // ---- Phase 3: warp MMA, 4m x 4n, warp tile 32x32 ----
    int wm = warp & 3;       // m offset wm*32
    int wn = warp >> 2;      // n offset wn*32

    float acc[2][4][4];
#pragma unroll
    for (int mt = 0; mt < 2; mt++)
#pragma unroll
        for (int nt = 0; nt < 4; nt++)
#pragma unroll
            for (int c = 0; c < 4; c++) acc[mt][nt][c] = 0.f;

#pragma unroll
    for (int ks = 0; ks < 16; ks++) {
        int k = ks * 8 + (lane & 3);
        uint32_t a[2][4];
#pragma unroll
        for (int mt = 0; mt < 2; mt++) {
            int m = wm * 32 + mt * 16 + (lane >> 2);
            a[mt][0] = sA[m * SA_STRIDE + k];
            a[mt][1] = sA[(m + 8) * SA_STRIDE + k];
            a[mt][2] = sA[m * SA_STRIDE + k + 4];
            a[mt][3] = sA[(m + 8) * SA_STRIDE + k + 4];
        }
#pragma unroll
        for (int nt = 0; nt < 4; nt++) {
            int n = wn * 32 + nt * 8 + (lane >> 2);
            uint32_t b0 = sW[n * SW_STRIDE + k];
            uint32_t b1 = sW[n * SW_STRIDE + k + 4];
#pragma unroll
            for (int mt = 0; mt < 2; mt++) {
                asm volatile(
                    "mma.sync.aligned.m16n8k8.row.col.f32.tf32.tf32.f32 "
                    "{%0,%1,%2,%3}, {%4,%5,%6,%7}, {%8,%9}, {%0,%1,%2,%3};"
                    : "+f"(acc[mt][nt][0]), "+f"(acc[mt][nt][1]),
                      "+f"(acc[mt][nt][2]), "+f"(acc[mt][nt][3])
                    : "r"(a[mt][0]), "r"(a[mt][1]),
                      "r"(a[mt][2]), "r"(a[mt][3]),
                      "r"(b0), "r"(b1));
            }
        }
    }

    // ---- epilogue: bias + store ----
#pragma unroll
    for (int mt = 0; mt < 2; mt++) {
        int r0 = row0 + wm * 32 + mt * 16 + (lane >> 2);
        int r1 = r0 + 8;
#pragma unroll
        for (int nt = 0; nt < 4; nt++) {
            int c = wn * 32 + nt * 8 + (lane & 3) * 2;
            float2 bb = __ldg((const float2*)&bias[c]);
            if (r0 < N_NODES) {
                float2 o = make_float2(acc[mt][nt][0] + bb.x,
                                       acc[mt][nt][1] + bb.y);
                *(float2*)&out[(size_t)r0 * DIM + c] = o;
            }
            if (r1 < N_NODES) {
                float2 o = make_float2(acc[mt][nt][2] + bb.x,
                                       acc[mt][nt][3] + bb.y);
                *(float2*)&out[(size_t)r1 * DIM + c] = o;
            }
        }
    }
}

// ---------------------------------------------------------------------------
// Launch
// ---------------------------------------------------------------------------
extern "C" void kernel_launch(void* const* d_in, const int* in_sizes, int n_in,
                              void* d_out, int out_size) {
    const float* h        = (const float*)d_in[0];
    const float* W        = (const float*)d_in[1];
    const float* b        = (const float*)d_in[2];
    const int*   edge_src = (const int*)d_in[3];
    const int*   edge_dst = (const int*)d_in[4];
    float*       out      = (float*)d_out;

    zero_deg_kernel<<<(N_NODES + 255) / 256, 256>>>();
    deg_kernel<<<(N_EDGES + 255) / 256, 256>>>(edge_dst);
    scan_block_kernel<<<NSCAN, SCAN_BS>>>();
    finalize_kernel<<<(N_NODES + 255) / 256, 256>>>();
    csr_scatter_kernel<<<(N_EDGES + 255) / 256, 256>>>(edge_src, edge_dst);

    (void)cudaFuncSetAttribute(fused_gather_gemm_kernel,
                               cudaFuncAttributeMaxDynamicSharedMemorySize,
                               SMEM_SZ);
    int tiles = (N_NODES + 127) / 128;   // 782
    fused_gather_gemm_kernel<<<tiles, 512, SMEM_SZ>>>(h, W, b, out);
}

// round 10
// speedup vs baseline: 1.2159x; 1.2159x over previous
#include <cuda_runtime.h>
#include <cuda_fp16.h>
#include <cstdint>

#define N_NODES 100000
#define N_EDGES 1600000
#define DIM     128
#define SCAN_BS 1024
#define NSCAN   ((N_NODES + SCAN_BS - 1) / SCAN_BS)   // 98

// Scratch (no cudaMalloc allowed)
__device__ float  g_agg[(size_t)N_NODES * DIM];     // normalized aggregate, fp32
__device__ __half g_h16[(size_t)N_NODES * DIM];     // fp16 copy of h
__device__ int    g_deg[N_NODES];
__device__ float  g_norm[N_NODES];
__device__ int    g_part[N_NODES];
__device__ int    g_bsum[NSCAN];
__device__ int    g_row_start[N_NODES + 1];
__device__ int    g_cursor[N_NODES];
__device__ int    g_sorted_src[N_EDGES];

// ---------------------------------------------------------------------------
// 0. convert h -> fp16 (8 floats per thread, 16B store)
// ---------------------------------------------------------------------------
__global__ void cvt_h_kernel(const float* __restrict__ h) {
    int i = blockIdx.x * blockDim.x + threadIdx.x;   // over N*DIM/8
    if (i >= N_NODES * DIM / 8) return;
    const float4* h4 = (const float4*)h;
    float4 a = __ldg(&h4[i * 2]);
    float4 b = __ldg(&h4[i * 2 + 1]);
    __half2 p0 = __floats2half2_rn(a.x, a.y);
    __half2 p1 = __floats2half2_rn(a.z, a.w);
    __half2 p2 = __floats2half2_rn(b.x, b.y);
    __half2 p3 = __floats2half2_rn(b.z, b.w);
    uint4 o;
    o.x = *(uint32_t*)&p0; o.y = *(uint32_t*)&p1;
    o.z = *(uint32_t*)&p2; o.w = *(uint32_t*)&p3;
    ((uint4*)g_h16)[i] = o;
}

// ---------------------------------------------------------------------------
// 1. zero degree counters
// ---------------------------------------------------------------------------
__global__ void zero_deg_kernel() {
    int i = blockIdx.x * blockDim.x + threadIdx.x;
    if (i < N_NODES) g_deg[i] = 0;
}

// ---------------------------------------------------------------------------
// 2. in-degree histogram
// ---------------------------------------------------------------------------
__global__ void deg_kernel(const int* __restrict__ edge_dst) {
    int i = blockIdx.x * blockDim.x + threadIdx.x;
    if (i < N_EDGES) atomicAdd(&g_deg[edge_dst[i]], 1);
}

// ---------------------------------------------------------------------------
// 3a. per-block exclusive scan of deg
// ---------------------------------------------------------------------------
__global__ __launch_bounds__(SCAN_BS)
void scan_block_kernel() {
    __shared__ int s[SCAN_BS];
    int tid = threadIdx.x;
    int gi  = blockIdx.x * SCAN_BS + tid;
    int v = (gi < N_NODES) ? g_deg[gi] : 0;
    s[tid] = v;
    __syncthreads();
#pragma unroll
    for (int off = 1; off < SCAN_BS; off <<= 1) {
        int t = (tid >= off) ? s[tid - off] : 0;
        __syncthreads();
        s[tid] += t;
        __syncthreads();
    }
    if (gi < N_NODES) g_part[gi] = s[tid] - v;
    if (tid == SCAN_BS - 1) g_bsum[blockIdx.x] = s[tid];
}

// ---------------------------------------------------------------------------
// 3b. finalize: re-scan block sums locally, build row_start/cursor/norm
// ---------------------------------------------------------------------------
__global__ __launch_bounds__(256)
void finalize_kernel() {
    __shared__ int ss[128];
    int tid = threadIdx.x;
    if (tid < 128) ss[tid] = (tid < NSCAN) ? g_bsum[tid] : 0;
    __syncthreads();
#pragma unroll
    for (int off = 1; off < 128; off <<= 1) {
        int t = (tid < 128 && tid >= off) ? ss[tid - off] : 0;
        __syncthreads();
        if (tid < 128) ss[tid] += t;
        __syncthreads();
    }
    int i = blockIdx.x * blockDim.x + tid;
    if (i < N_NODES) {
        int reg = i / SCAN_BS;
        int boff = (reg == 0) ? 0 : ss[reg - 1];
        int rs = g_part[i] + boff;
        g_row_start[i] = rs;
        g_cursor[i]    = rs;
        int d = g_deg[i];
        g_norm[i] = rsqrtf((float)(d > 0 ? d : 1));
    }
    if (i == 0) g_row_start[N_NODES] = N_EDGES;
}

// ---------------------------------------------------------------------------
// 4. bucket edges by dst
// ---------------------------------------------------------------------------
__global__ void csr_scatter_kernel(const int* __restrict__ edge_src,
                                   const int* __restrict__ edge_dst) {
    int e = blockIdx.x * blockDim.x + threadIdx.x;
    if (e < N_EDGES) {
        int d = edge_dst[e];
        int pos = atomicAdd(&g_cursor[d], 1);
        g_sorted_src[pos] = edge_src[e];
    }
}

// ---------------------------------------------------------------------------
// 5. gather-aggregate over fp16 h: one warp per node, no atomics.
//    Lane reads 8B (4 halves) per edge; warp reads the 256B row.
// ---------------------------------------------------------------------------
__global__ __launch_bounds__(256)
void gather_kernel() {
    int warp = (blockIdx.x * blockDim.x + threadIdx.x) >> 5;
    int lane = threadIdx.x & 31;
    if (warp >= N_NODES) return;

    int start = __ldg(&g_row_start[warp]);
    int end   = __ldg(&g_row_start[warp + 1]);

    const uint2* h2 = (const uint2*)g_h16;   // 32 uint2 per row
    float4 acc = make_float4(0.f, 0.f, 0.f, 0.f);

    int e = start;
    for (; e + 3 < end; e += 4) {
        int s0 = __ldg(&g_sorted_src[e]);
        int s1 = __ldg(&g_sorted_src[e + 1]);
        int s2 = __ldg(&g_sorted_src[e + 2]);
        int s3 = __ldg(&g_sorted_src[e + 3]);
        float n0 = __ldg(&g_norm[s0]);
        float n1 = __ldg(&g_norm[s1]);
        float n2 = __ldg(&g_norm[s2]);
        float n3 = __ldg(&g_norm[s3]);
        uint2 u0 = __ldg(&h2[(size_t)s0 * 32 + lane]);
        uint2 u1 = __ldg(&h2[(size_t)s1 * 32 + lane]);
        uint2 u2 = __ldg(&h2[(size_t)s2 * 32 + lane]);
        uint2 u3 = __ldg(&h2[(size_t)s3 * 32 + lane]);
        float2 a0 = __half22float2(*(__half2*)&u0.x);
        float2 b0 = __half22float2(*(__half2*)&u0.y);
        float2 a1 = __half22float2(*(__half2*)&u1.x);
        float2 b1 = __half22float2(*(__half2*)&u1.y);
        float2 a2 = __half22float2(*(__half2*)&u2.x);
        float2 b2 = __half22float2(*(__half2*)&u2.y);
        float2 a3 = __half22float2(*(__half2*)&u3.x);
        float2 b3 = __half22float2(*(__half2*)&u3.y);
        acc.x += a0.x * n0 + a1.x * n1 + a2.x * n2 + a3.x * n3;
        acc.y += a0.y * n0 + a1.y * n1 + a2.y * n2 + a3.y * n3;
        acc.z += b0.x * n0 + b1.x * n1 + b2.x * n2 + b3.x * n3;
        acc.w += b0.y * n0 + b1.y * n1 + b2.y * n2 + b3.y * n3;
    }
    for (; e < end; e++) {
        int s0 = __ldg(&g_sorted_src[e]);
        float n0 = __ldg(&g_norm[s0]);
        uint2 u0 = __ldg(&h2[(size_t)s0 * 32 + lane]);
        float2 a0 = __half22float2(*(__half2*)&u0.x);
        float2 b0 = __half22float2(*(__half2*)&u0.y);
        acc.x += a0.x * n0; acc.y += a0.y * n0;
        acc.z += b0.x * n0; acc.w += b0.y * n0;
    }

    float nd = __ldg(&g_norm[warp]);
    acc.x *= nd; acc.y *= nd; acc.z *= nd; acc.w *= nd;
    // lane owns 4 contiguous floats at col lane*4 -> float4 index warp*32+lane
    ((float4*)g_agg)[(size_t)warp * 32 + lane] = acc;
}

// ---------------------------------------------------------------------------
// 6. tf32 warp-MMA GEMM (verified in R6): out = aggn @ W^T + b
// ---------------------------------------------------------------------------
#define SW_STRIDE 132
#define SA_STRIDE 36
#define SMEM_W_WORDS (128 * SW_STRIDE)
#define SMEM_A_WORDS (128 * SA_STRIDE)
#define SMEM_SZ ((SMEM_W_WORDS + SMEM_A_WORDS) * 4)   // 86016 B

__device__ __forceinline__ uint32_t f2tf32(float f) {
    uint32_t r;
    asm("cvt.rna.tf32.f32 %0, %1;" : "=r"(r) : "f"(f));
    return r;
}

__global__ __launch_bounds__(256)
void mma_gemm_kernel(const float* __restrict__ W,
                     const float* __restrict__ bias,
                     float*       __restrict__ out) {
    extern __shared__ uint32_t sm[];
    uint32_t* sW = sm;                  // [n][k], tf32 bits
    uint32_t* sA = sm + SMEM_W_WORDS;   // [m][k-chunk], tf32 bits

    int tid  = threadIdx.x;
    int lane = tid & 31;
    int warp = tid >> 5;
    int wm   = warp & 3;
    int wn   = warp >> 2;
    int row0 = blockIdx.x * 128;

    {
        const float4* W4 = (const float4*)W;
#pragma unroll
        for (int t = tid; t < 4096; t += 256) {
            int n = t >> 5;
            int q = t & 31;
            float4 w = __ldg(&W4[n * 32 + q]);
            uint32_t* p = &sW[n * SW_STRIDE + q * 4];
            p[0] = f2tf32(w.x); p[1] = f2tf32(w.y);
            p[2] = f2tf32(w.z); p[3] = f2tf32(w.w);
        }
    }

    float acc[2][8][4];
#pragma unroll
    for (int mt = 0; mt < 2; mt++)
#pragma unroll
        for (int nt = 0; nt < 8; nt++)
#pragma unroll
            for (int c = 0; c < 4; c++) acc[mt][nt][c] = 0.f;

    const float4* A4 = (const float4*)g_agg;

    for (int kc = 0; kc < DIM; kc += 32) {
        __syncthreads();
#pragma unroll
        for (int t = tid; t < 1024; t += 256) {
            int m = t >> 3;
            int q = t & 7;
            int row = row0 + m;
            float4 a = make_float4(0.f, 0.f, 0.f, 0.f);
            if (row < N_NODES)
                a = __ldg(&A4[(size_t)row * 32 + (kc >> 2) + q]);
            uint32_t* p = &sA[m * SA_STRIDE + q * 4];
            p[0] = f2tf32(a.x); p[1] = f2tf32(a.y);
            p[2] = f2tf32(a.z); p[3] = f2tf32(a.w);
        }
        __syncthreads();

#pragma unroll
        for (int ks = 0; ks < 4; ks++) {
            int k = ks * 8 + (lane & 3);
            uint32_t a[2][4];
#pragma unroll
            for (int mt = 0; mt < 2; mt++) {
                int m = wm * 32 + mt * 16 + (lane >> 2);
                a[mt][0] = sA[m * SA_STRIDE + k];
                a[mt][1] = sA[(m + 8) * SA_STRIDE + k];
                a[mt][2] = sA[m * SA_STRIDE + k + 4];
                a[mt][3] = sA[(m + 8) * SA_STRIDE + k + 4];
            }
#pragma unroll
            for (int nt = 0; nt < 8; nt++) {
                int n = wn * 64 + nt * 8 + (lane >> 2);
                uint32_t b0 = sW[n * SW_STRIDE + kc + k];
                uint32_t b1 = sW[n * SW_STRIDE + kc + k + 4];
#pragma unroll
                for (int mt = 0; mt < 2; mt++) {
                    asm volatile(
                        "mma.sync.aligned.m16n8k8.row.col.f32.tf32.tf32.f32 "
                        "{%0,%1,%2,%3}, {%4,%5,%6,%7}, {%8,%9}, {%0,%1,%2,%3};"
                        : "+f"(acc[mt][nt][0]), "+f"(acc[mt][nt][1]),
                          "+f"(acc[mt][nt][2]), "+f"(acc[mt][nt][3])
                        : "r"(a[mt][0]), "r"(a[mt][1]),
                          "r"(a[mt][2]), "r"(a[mt][3]),
                          "r"(b0), "r"(b1));
                }
            }
        }
    }

#pragma unroll
    for (int mt = 0; mt < 2; mt++) {
        int r0 = row0 + wm * 32 + mt * 16 + (lane >> 2);
        int r1 = r0 + 8;
#pragma unroll
        for (int nt = 0; nt < 8; nt++) {
            int c = wn * 64 + nt * 8 + (lane & 3) * 2;
            float2 bb = __ldg((const float2*)&bias[c]);
            if (r0 < N_NODES) {
                float2 o = make_float2(acc[mt][nt][0] + bb.x,
                                       acc[mt][nt][1] + bb.y);
                *(float2*)&out[(size_t)r0 * DIM + c] = o;
            }
            if (r1 < N_NODES) {
                float2 o = make_float2(acc[mt][nt][2] + bb.x,
                                       acc[mt][nt][3] + bb.y);
                *(float2*)&out[(size_t)r1 * DIM + c] = o;
            }
        }
    }
}

// ---------------------------------------------------------------------------
// Launch
// ---------------------------------------------------------------------------
extern "C" void kernel_launch(void* const* d_in, const int* in_sizes, int n_in,
                              void* d_out, int out_size) {
    const float* h        = (const float*)d_in[0];
    const float* W        = (const float*)d_in[1];
    const float* b        = (const float*)d_in[2];
    const int*   edge_src = (const int*)d_in[3];
    const int*   edge_dst = (const int*)d_in[4];
    float*       out      = (float*)d_out;

    cvt_h_kernel<<<(N_NODES * DIM / 8 + 255) / 256, 256>>>(h);
    zero_deg_kernel<<<(N_NODES + 255) / 256, 256>>>();
    deg_kernel<<<(N_EDGES + 255) / 256, 256>>>(edge_dst);
    scan_block_kernel<<<NSCAN, SCAN_BS>>>();
    finalize_kernel<<<(N_NODES + 255) / 256, 256>>>();
    csr_scatter_kernel<<<(N_EDGES + 255) / 256, 256>>>(edge_src, edge_dst);

    {   // one warp per node
        int blocks = (N_NODES + 7) / 8;
        gather_kernel<<<blocks, 256>>>();
    }

    (void)cudaFuncSetAttribute(mma_gemm_kernel,
                               cudaFuncAttributeMaxDynamicSharedMemorySize,
                               SMEM_SZ);
    int tiles = (N_NODES + 127) / 128;   // 782
    mma_gemm_kernel<<<tiles, 256, SMEM_SZ>>>(W, b, out);
}

// round 11
// speedup vs baseline: 1.3234x; 1.0884x over previous
#include <cuda_runtime.h>
#include <cuda_fp16.h>
#include <cstdint>

#define N_NODES 100000
#define N_EDGES 1600000
#define DIM     128
#define SCAN_BS 1024
#define NSCAN   ((N_NODES + SCAN_BS - 1) / SCAN_BS)   // 98

// Scratch (no cudaMalloc allowed)
__device__ uint32_t g_agg[(size_t)N_NODES * DIM];   // tf32 bits of normalized aggregate
__device__ __half   g_h16[(size_t)N_NODES * DIM];   // fp16 h prescaled by norm[row]
__device__ int      g_deg[N_NODES];
__device__ float    g_norm[N_NODES];
__device__ int      g_part[N_NODES];
__device__ int      g_bsum[NSCAN];
__device__ int      g_row_start[N_NODES + 1];
__device__ int      g_cursor[N_NODES];
__device__ int      g_sorted_src[N_EDGES];

// ---------------------------------------------------------------------------
// 1. zero degree counters
// ---------------------------------------------------------------------------
__global__ void zero_deg_kernel() {
    int i = blockIdx.x * blockDim.x + threadIdx.x;
    if (i < N_NODES) g_deg[i] = 0;
}

// ---------------------------------------------------------------------------
// 2. in-degree histogram
// ---------------------------------------------------------------------------
__global__ void deg_kernel(const int* __restrict__ edge_dst) {
    int i = blockIdx.x * blockDim.x + threadIdx.x;
    if (i < N_EDGES) atomicAdd(&g_deg[edge_dst[i]], 1);
}

// ---------------------------------------------------------------------------
// 3a. per-block exclusive scan of deg
// ---------------------------------------------------------------------------
__global__ __launch_bounds__(SCAN_BS)
void scan_block_kernel() {
    __shared__ int s[SCAN_BS];
    int tid = threadIdx.x;
    int gi  = blockIdx.x * SCAN_BS + tid;
    int v = (gi < N_NODES) ? g_deg[gi] : 0;
    s[tid] = v;
    __syncthreads();
#pragma unroll
    for (int off = 1; off < SCAN_BS; off <<= 1) {
        int t = (tid >= off) ? s[tid - off] : 0;
        __syncthreads();
        s[tid] += t;
        __syncthreads();
    }
    if (gi < N_NODES) g_part[gi] = s[tid] - v;
    if (tid == SCAN_BS - 1) g_bsum[blockIdx.x] = s[tid];
}

// ---------------------------------------------------------------------------
// 3b. finalize: re-scan block sums locally, build row_start/cursor/norm
// ---------------------------------------------------------------------------
__global__ __launch_bounds__(256)
void finalize_kernel() {
    __shared__ int ss[128];
    int tid = threadIdx.x;
    if (tid < 128) ss[tid] = (tid < NSCAN) ? g_bsum[tid] : 0;
    __syncthreads();
#pragma unroll
    for (int off = 1; off < 128; off <<= 1) {
        int t = (tid < 128 && tid >= off) ? ss[tid - off] : 0;
        __syncthreads();
        if (tid < 128) ss[tid] += t;
        __syncthreads();
    }
    int i = blockIdx.x * blockDim.x + tid;
    if (i < N_NODES) {
        int reg = i / SCAN_BS;
        int boff = (reg == 0) ? 0 : ss[reg - 1];
        int rs = g_part[i] + boff;
        g_row_start[i] = rs;
        g_cursor[i]    = rs;
        int d = g_deg[i];
        g_norm[i] = rsqrtf((float)(d > 0 ? d : 1));
    }
    if (i == 0) g_row_start[N_NODES] = N_EDGES;
}

// ---------------------------------------------------------------------------
// 4a. bucket edges by dst
// ---------------------------------------------------------------------------
__global__ void csr_scatter_kernel(const int* __restrict__ edge_src,
                                   const int* __restrict__ edge_dst) {
    int e = blockIdx.x * blockDim.x + threadIdx.x;
    if (e < N_EDGES) {
        int d = edge_dst[e];
        int pos = atomicAdd(&g_cursor[d], 1);
        g_sorted_src[pos] = edge_src[e];
    }
}

// ---------------------------------------------------------------------------
// 4b. convert h -> fp16 PRESCALED by norm[row] (after finalize)
//     thread handles 8 floats; row = group >> 4.
// ---------------------------------------------------------------------------
__global__ void cvt_h_kernel(const float* __restrict__ h) {
    int i = blockIdx.x * blockDim.x + threadIdx.x;   // over N*DIM/8
    if (i >= N_NODES * DIM / 8) return;
    float nr = __ldg(&g_norm[i >> 4]);
    const float4* h4 = (const float4*)h;
    float4 a = __ldg(&h4[i * 2]);
    float4 b = __ldg(&h4[i * 2 + 1]);
    __half2 p0 = __floats2half2_rn(a.x * nr, a.y * nr);
    __half2 p1 = __floats2half2_rn(a.z * nr, a.w * nr);
    __half2 p2 = __floats2half2_rn(b.x * nr, b.y * nr);
    __half2 p3 = __floats2half2_rn(b.z * nr, b.w * nr);
    uint4 o;
    o.x = *(uint32_t*)&p0; o.y = *(uint32_t*)&p1;
    o.z = *(uint32_t*)&p2; o.w = *(uint32_t*)&p3;
    ((uint4*)g_h16)[i] = o;
}

// ---------------------------------------------------------------------------
// 5. gather-aggregate: one warp per node, no atomics, no per-edge scaling.
//    acc = sum of prescaled rows; result *= norm[dst]; store tf32 bits.
// ---------------------------------------------------------------------------
__device__ __forceinline__ uint32_t f2tf32(float f) {
    uint32_t r;
    asm("cvt.rna.tf32.f32 %0, %1;" : "=r"(r) : "f"(f));
    return r;
}

__global__ __launch_bounds__(256)
void gather_kernel() {
    int warp = (blockIdx.x * blockDim.x + threadIdx.x) >> 5;
    int lane = threadIdx.x & 31;
    if (warp >= N_NODES) return;

    int start = __ldg(&g_row_start[warp]);
    int end   = __ldg(&g_row_start[warp + 1]);

    const uint2* h2 = (const uint2*)g_h16;   // 32 uint2 per row
    float4 acc = make_float4(0.f, 0.f, 0.f, 0.f);

    int e = start;
    for (; e + 3 < end; e += 4) {
        int s0 = __ldg(&g_sorted_src[e]);
        int s1 = __ldg(&g_sorted_src[e + 1]);
        int s2 = __ldg(&g_sorted_src[e + 2]);
        int s3 = __ldg(&g_sorted_src[e + 3]);
        uint2 u0 = __ldg(&h2[(size_t)s0 * 32 + lane]);
        uint2 u1 = __ldg(&h2[(size_t)s1 * 32 + lane]);
        uint2 u2 = __ldg(&h2[(size_t)s2 * 32 + lane]);
        uint2 u3 = __ldg(&h2[(size_t)s3 * 32 + lane]);
        float2 a0 = __half22float2(*(__half2*)&u0.x);
        float2 b0 = __half22float2(*(__half2*)&u0.y);
        float2 a1 = __half22float2(*(__half2*)&u1.x);
        float2 b1 = __half22float2(*(__half2*)&u1.y);
        float2 a2 = __half22float2(*(__half2*)&u2.x);
        float2 b2 = __half22float2(*(__half2*)&u2.y);
        float2 a3 = __half22float2(*(__half2*)&u3.x);
        float2 b3 = __half22float2(*(__half2*)&u3.y);
        acc.x += (a0.x + a1.x) + (a2.x + a3.x);
        acc.y += (a0.y + a1.y) + (a2.y + a3.y);
        acc.z += (b0.x + b1.x) + (b2.x + b3.x);
        acc.w += (b0.y + b1.y) + (b2.y + b3.y);
    }
    for (; e < end; e++) {
        int s0 = __ldg(&g_sorted_src[e]);
        uint2 u0 = __ldg(&h2[(size_t)s0 * 32 + lane]);
        float2 a0 = __half22float2(*(__half2*)&u0.x);
        float2 b0 = __half22float2(*(__half2*)&u0.y);
        acc.x += a0.x; acc.y += a0.y;
        acc.z += b0.x; acc.w += b0.y;
    }

    float nd = __ldg(&g_norm[warp]);
    uint4 o;
    o.x = f2tf32(acc.x * nd);
    o.y = f2tf32(acc.y * nd);
    o.z = f2tf32(acc.z * nd);
    o.w = f2tf32(acc.w * nd);
    ((uint4*)g_agg)[(size_t)warp * 32 + lane] = o;
}

// ---------------------------------------------------------------------------
// 6. tf32 warp-MMA GEMM: out = aggn @ W^T + b  (A already tf32 bits)
// ---------------------------------------------------------------------------
#define SW_STRIDE 132
#define SA_STRIDE 36
#define SMEM_W_WORDS (128 * SW_STRIDE)
#define SMEM_A_WORDS (128 * SA_STRIDE)
#define SMEM_SZ ((SMEM_W_WORDS + SMEM_A_WORDS) * 4)   // 86016 B

__global__ __launch_bounds__(256)
void mma_gemm_kernel(const float* __restrict__ W,
                     const float* __restrict__ bias,
                     float*       __restrict__ out) {
    extern __shared__ uint32_t sm[];
    uint32_t* sW = sm;                  // [n][k], tf32 bits
    uint32_t* sA = sm + SMEM_W_WORDS;   // [m][k-chunk], tf32 bits

    int tid  = threadIdx.x;
    int lane = tid & 31;
    int warp = tid >> 5;
    int wm   = warp & 3;
    int wn   = warp >> 2;
    int row0 = blockIdx.x * 128;

    {
        const float4* W4 = (const float4*)W;
#pragma unroll
        for (int t = tid; t < 4096; t += 256) {
            int n = t >> 5;
            int q = t & 31;
            float4 w = __ldg(&W4[n * 32 + q]);
            uint32_t* p = &sW[n * SW_STRIDE + q * 4];
            p[0] = f2tf32(w.x); p[1] = f2tf32(w.y);
            p[2] = f2tf32(w.z); p[3] = f2tf32(w.w);
        }
    }

    float acc[2][8][4];
#pragma unroll
    for (int mt = 0; mt < 2; mt++)
#pragma unroll
        for (int nt = 0; nt < 8; nt++)
#pragma unroll
            for (int c = 0; c < 4; c++) acc[mt][nt][c] = 0.f;

    const uint4* A4 = (const uint4*)g_agg;

    for (int kc = 0; kc < DIM; kc += 32) {
        __syncthreads();
#pragma unroll
        for (int t = tid; t < 1024; t += 256) {
            int m = t >> 3;
            int q = t & 7;
            int row = row0 + m;
            uint4 a = make_uint4(0u, 0u, 0u, 0u);
            if (row < N_NODES)
                a = __ldg(&A4[(size_t)row * 32 + (kc >> 2) + q]);
            uint32_t* p = &sA[m * SA_STRIDE + q * 4];
            p[0] = a.x; p[1] = a.y; p[2] = a.z; p[3] = a.w;
        }
        __syncthreads();

#pragma unroll
        for (int ks = 0; ks < 4; ks++) {
            int k = ks * 8 + (lane & 3);
            uint32_t a[2][4];
#pragma unroll
            for (int mt = 0; mt < 2; mt++) {
                int m = wm * 32 + mt * 16 + (lane >> 2);
                a[mt][0] = sA[m * SA_STRIDE + k];
                a[mt][1] = sA[(m + 8) * SA_STRIDE + k];
                a[mt][2] = sA[m * SA_STRIDE + k + 4];
                a[mt][3] = sA[(m + 8) * SA_STRIDE + k + 4];
            }
#pragma unroll
            for (int nt = 0; nt < 8; nt++) {
                int n = wn * 64 + nt * 8 + (lane >> 2);
                uint32_t b0 = sW[n * SW_STRIDE + kc + k];
                uint32_t b1 = sW[n * SW_STRIDE + kc + k + 4];
#pragma unroll
                for (int mt = 0; mt < 2; mt++) {
                    asm volatile(
                        "mma.sync.aligned.m16n8k8.row.col.f32.tf32.tf32.f32 "
                        "{%0,%1,%2,%3}, {%4,%5,%6,%7}, {%8,%9}, {%0,%1,%2,%3};"
                        : "+f"(acc[mt][nt][0]), "+f"(acc[mt][nt][1]),
                          "+f"(acc[mt][nt][2]), "+f"(acc[mt][nt][3])
                        : "r"(a[mt][0]), "r"(a[mt][1]),
                          "r"(a[mt][2]), "r"(a[mt][3]),
                          "r"(b0), "r"(b1));
                }
            }
        }
    }

#pragma unroll
    for (int mt = 0; mt < 2; mt++) {
        int r0 = row0 + wm * 32 + mt * 16 + (lane >> 2);
        int r1 = r0 + 8;
#pragma unroll
        for (int nt = 0; nt < 8; nt++) {
            int c = wn * 64 + nt * 8 + (lane & 3) * 2;
            float2 bb = __ldg((const float2*)&bias[c]);
            if (r0 < N_NODES) {
                float2 o = make_float2(acc[mt][nt][0] + bb.x,
                                       acc[mt][nt][1] + bb.y);
                *(float2*)&out[(size_t)r0 * DIM + c] = o;
            }
            if (r1 < N_NODES) {
                float2 o = make_float2(acc[mt][nt][2] + bb.x,
                                       acc[mt][nt][3] + bb.y);
                *(float2*)&out[(size_t)r1 * DIM + c] = o;
            }
        }
    }
}

// ---------------------------------------------------------------------------
// Launch
// ---------------------------------------------------------------------------
extern "C" void kernel_launch(void* const* d_in, const int* in_sizes, int n_in,
                              void* d_out, int out_size) {
    const float* h        = (const float*)d_in[0];
    const float* W        = (const float*)d_in[1];
    const float* b        = (const float*)d_in[2];
    const int*   edge_src = (const int*)d_in[3];
    const int*   edge_dst = (const int*)d_in[4];
    float*       out      = (float*)d_out;

    zero_deg_kernel<<<(N_NODES + 255) / 256, 256>>>();
    deg_kernel<<<(N_EDGES + 255) / 256, 256>>>(edge_dst);
    scan_block_kernel<<<NSCAN, SCAN_BS>>>();
    finalize_kernel<<<(N_NODES + 255) / 256, 256>>>();
    csr_scatter_kernel<<<(N_EDGES + 255) / 256, 256>>>(edge_src, edge_dst);
    cvt_h_kernel<<<(N_NODES * DIM / 8 + 255) / 256, 256>>>(h);

    {   // one warp per node
        int blocks = (N_NODES + 7) / 8;
        gather_kernel<<<blocks, 256>>>();
    }

    (void)cudaFuncSetAttribute(mma_gemm_kernel,
                               cudaFuncAttributeMaxDynamicSharedMemorySize,
                               SMEM_SZ);
    int tiles = (N_NODES + 127) / 128;   // 782
    mma_gemm_kernel<<<tiles, 256, SMEM_SZ>>>(W, b, out);
}

// round 12
// speedup vs baseline: 1.6010x; 1.2098x over previous
#include <cuda_runtime.h>
#include <cuda_fp16.h>
#include <cstdint>

#define N_NODES 100000
#define N_EDGES 1600000
#define DIM     128
#define SCAN_BS 1024
#define NSCAN   ((N_NODES + SCAN_BS - 1) / SCAN_BS)   // 98

// Scratch (no cudaMalloc allowed)
__device__ __half   g_agg16[(size_t)N_NODES * DIM];  // fp16 normalized aggregate
__device__ __half   g_h16[(size_t)N_NODES * DIM];    // fp16 h prescaled by norm[row]
__device__ int      g_deg[N_NODES];
__device__ float    g_norm[N_NODES];
__device__ int      g_part[N_NODES];
__device__ int      g_bsum[NSCAN];
__device__ int      g_row_start[N_NODES + 1];
__device__ int      g_cursor[N_NODES];
__device__ int      g_sorted_src[N_EDGES];

// ---------------------------------------------------------------------------
// 1. zero degree counters
// ---------------------------------------------------------------------------
__global__ void zero_deg_kernel() {
    int i = blockIdx.x * blockDim.x + threadIdx.x;
    if (i < N_NODES) g_deg[i] = 0;
}

// ---------------------------------------------------------------------------
// 2. in-degree histogram
// ---------------------------------------------------------------------------
__global__ void deg_kernel(const int* __restrict__ edge_dst) {
    int i = blockIdx.x * blockDim.x + threadIdx.x;
    if (i < N_EDGES) atomicAdd(&g_deg[edge_dst[i]], 1);
}

// ---------------------------------------------------------------------------
// 3a. per-block exclusive scan of deg
// ---------------------------------------------------------------------------
__global__ __launch_bounds__(SCAN_BS)
void scan_block_kernel() {
    __shared__ int s[SCAN_BS];
    int tid = threadIdx.x;
    int gi  = blockIdx.x * SCAN_BS + tid;
    int v = (gi < N_NODES) ? g_deg[gi] : 0;
    s[tid] = v;
    __syncthreads();
#pragma unroll
    for (int off = 1; off < SCAN_BS; off <<= 1) {
        int t = (tid >= off) ? s[tid - off] : 0;
        __syncthreads();
        s[tid] += t;
        __syncthreads();
    }
    if (gi < N_NODES) g_part[gi] = s[tid] - v;
    if (tid == SCAN_BS - 1) g_bsum[blockIdx.x] = s[tid];
}

// ---------------------------------------------------------------------------
// 3b. finalize: re-scan block sums locally, build row_start/cursor/norm
// ---------------------------------------------------------------------------
__global__ __launch_bounds__(256)
void finalize_kernel() {
    __shared__ int ss[128];
    int tid = threadIdx.x;
    if (tid < 128) ss[tid] = (tid < NSCAN) ? g_bsum[tid] : 0;
    __syncthreads();
#pragma unroll
    for (int off = 1; off < 128; off <<= 1) {
        int t = (tid < 128 && tid >= off) ? ss[tid - off] : 0;
        __syncthreads();
        if (tid < 128) ss[tid] += t;
        __syncthreads();
    }
    int i = blockIdx.x * blockDim.x + tid;
    if (i < N_NODES) {
        int reg = i / SCAN_BS;
        int boff = (reg == 0) ? 0 : ss[reg - 1];
        int rs = g_part[i] + boff;
        g_row_start[i] = rs;
        g_cursor[i]    = rs;
        int d = g_deg[i];
        g_norm[i] = rsqrtf((float)(d > 0 ? d : 1));
    }
    if (i == 0) g_row_start[N_NODES] = N_EDGES;
}

// ---------------------------------------------------------------------------
// 4a. bucket edges by dst
// ---------------------------------------------------------------------------
__global__ void csr_scatter_kernel(const int* __restrict__ edge_src,
                                   const int* __restrict__ edge_dst) {
    int e = blockIdx.x * blockDim.x + threadIdx.x;
    if (e < N_EDGES) {
        int d = edge_dst[e];
        int pos = atomicAdd(&g_cursor[d], 1);
        g_sorted_src[pos] = edge_src[e];
    }
}

// ---------------------------------------------------------------------------
// 4b. convert h -> fp16 PRESCALED by norm[row]
// ---------------------------------------------------------------------------
__global__ void cvt_h_kernel(const float* __restrict__ h) {
    int i = blockIdx.x * blockDim.x + threadIdx.x;   // over N*DIM/8
    if (i >= N_NODES * DIM / 8) return;
    float nr = __ldg(&g_norm[i >> 4]);
    const float4* h4 = (const float4*)h;
    float4 a = __ldg(&h4[i * 2]);
    float4 b = __ldg(&h4[i * 2 + 1]);
    __half2 p0 = __floats2half2_rn(a.x * nr, a.y * nr);
    __half2 p1 = __floats2half2_rn(a.z * nr, a.w * nr);
    __half2 p2 = __floats2half2_rn(b.x * nr, b.y * nr);
    __half2 p3 = __floats2half2_rn(b.z * nr, b.w * nr);
    uint4 o;
    o.x = *(uint32_t*)&p0; o.y = *(uint32_t*)&p1;
    o.z = *(uint32_t*)&p2; o.w = *(uint32_t*)&p3;
    ((uint4*)g_h16)[i] = o;
}

// ---------------------------------------------------------------------------
// 5. gather-aggregate: one warp per node, fp32 acc, fp16 store
// ---------------------------------------------------------------------------
__global__ __launch_bounds__(256)
void gather_kernel() {
    int warp = (blockIdx.x * blockDim.x + threadIdx.x) >> 5;
    int lane = threadIdx.x & 31;
    if (warp >= N_NODES) return;

    int start = __ldg(&g_row_start[warp]);
    int end   = __ldg(&g_row_start[warp + 1]);

    const uint2* h2 = (const uint2*)g_h16;   // 32 uint2 per row
    float4 acc = make_float4(0.f, 0.f, 0.f, 0.f);

    int e = start;
    for (; e + 3 < end; e += 4) {
        int s0 = __ldg(&g_sorted_src[e]);
        int s1 = __ldg(&g_sorted_src[e + 1]);
        int s2 = __ldg(&g_sorted_src[e + 2]);
        int s3 = __ldg(&g_sorted_src[e + 3]);
        uint2 u0 = __ldg(&h2[(size_t)s0 * 32 + lane]);
        uint2 u1 = __ldg(&h2[(size_t)s1 * 32 + lane]);
        uint2 u2 = __ldg(&h2[(size_t)s2 * 32 + lane]);
        uint2 u3 = __ldg(&h2[(size_t)s3 * 32 + lane]);
        float2 a0 = __half22float2(*(__half2*)&u0.x);
        float2 b0 = __half22float2(*(__half2*)&u0.y);
        float2 a1 = __half22float2(*(__half2*)&u1.x);
        float2 b1 = __half22float2(*(__half2*)&u1.y);
        float2 a2 = __half22float2(*(__half2*)&u2.x);
        float2 b2 = __half22float2(*(__half2*)&u2.y);
        float2 a3 = __half22float2(*(__half2*)&u3.x);
        float2 b3 = __half22float2(*(__half2*)&u3.y);
        acc.x += (a0.x + a1.x) + (a2.x + a3.x);
        acc.y += (a0.y + a1.y) + (a2.y + a3.y);
        acc.z += (b0.x + b1.x) + (b2.x + b3.x);
        acc.w += (b0.y + b1.y) + (b2.y + b3.y);
    }
    for (; e < end; e++) {
        int s0 = __ldg(&g_sorted_src[e]);
        uint2 u0 = __ldg(&h2[(size_t)s0 * 32 + lane]);
        float2 a0 = __half22float2(*(__half2*)&u0.x);
        float2 b0 = __half22float2(*(__half2*)&u0.y);
        acc.x += a0.x; acc.y += a0.y;
        acc.z += b0.x; acc.w += b0.y;
    }

    float nd = __ldg(&g_norm[warp]);
    __half2 p0 = __floats2half2_rn(acc.x * nd, acc.y * nd);
    __half2 p1 = __floats2half2_rn(acc.z * nd, acc.w * nd);
    uint2 o;
    o.x = *(uint32_t*)&p0;
    o.y = *(uint32_t*)&p1;
    ((uint2*)g_agg16)[(size_t)warp * 32 + lane] = o;
}

// ---------------------------------------------------------------------------
// 6. fp16 ldmatrix MMA GEMM: out = aggn @ W^T + b
//    m16n8k16, fp32 acc. 8 warps: 4m x 2n, warp tile 32x64.
//    smem half-stride 136 (272B rows) -> ldmatrix conflict-free.
// ---------------------------------------------------------------------------
#define SH_STRIDE 136
#define SMEM_HALF_W (128 * SH_STRIDE)                 // halves
#define SMEM_SZ (2 * SMEM_HALF_W * 2)                 // 69632 B

#define LDSM_X4(r0, r1, r2, r3, addr) \
    asm volatile("ldmatrix.sync.aligned.m8n8.x4.shared.b16 {%0,%1,%2,%3}, [%4];" \
        : "=r"(r0), "=r"(r1), "=r"(r2), "=r"(r3) : "r"(addr))

__global__ __launch_bounds__(256)
void mma_gemm_kernel(const float* __restrict__ W,
                     const float* __restrict__ bias,
                     float*       __restrict__ out) {
    extern __shared__ __half smh[];
    __half* sW = smh;                    // [n][k]
    __half* sA = smh + SMEM_HALF_W;      // [m][k]

    int tid  = threadIdx.x;
    int lane = tid & 31;
    int warp = tid >> 5;
    int wm   = warp & 3;      // m0 = wm*32
    int wn   = warp >> 2;     // n0 = wn*64
    int row0 = blockIdx.x * 128;

    // ---- stage W as fp16 ----
    {
        const float4* W4 = (const float4*)W;
#pragma unroll
        for (int t = tid; t < 4096; t += 256) {
            int n = t >> 5;
            int q = t & 31;
            float4 w = __ldg(&W4[n * 32 + q]);
            __half2 h0 = __floats2half2_rn(w.x, w.y);
            __half2 h1 = __floats2half2_rn(w.z, w.w);
            uint32_t* p = (uint32_t*)&sW[n * SH_STRIDE + q * 4];
            p[0] = *(uint32_t*)&h0;
            p[1] = *(uint32_t*)&h1;
        }
    }
    // ---- stage A (fp16 bit-copy) ----
    {
        const uint2* A2 = (const uint2*)g_agg16;
#pragma unroll
        for (int t = tid; t < 4096; t += 256) {
            int m = t >> 5;
            int q = t & 31;
            int row = row0 + m;
            uint2 a = make_uint2(0u, 0u);
            if (row < N_NODES) a = __ldg(&A2[(size_t)row * 32 + q]);
            uint32_t* p = (uint32_t*)&sA[m * SH_STRIDE + q * 4];
            p[0] = a.x;
            p[1] = a.y;
        }
    }
    __syncthreads();

    float acc[2][8][4];
#pragma unroll
    for (int mt = 0; mt < 2; mt++)
#pragma unroll
        for (int nt = 0; nt < 8; nt++)
#pragma unroll
            for (int c = 0; c < 4; c++) acc[mt][nt][c] = 0.f;

    uint32_t sA_base = (uint32_t)__cvta_generic_to_shared(sA);
    uint32_t sW_base = (uint32_t)__cvta_generic_to_shared(sW);

#pragma unroll
    for (int ks = 0; ks < 8; ks++) {
        int k0 = ks * 16;
        // A fragments: x4 ldmatrix per 16x16 tile
        uint32_t a[2][4];
#pragma unroll
        for (int mt = 0; mt < 2; mt++) {
            int r = wm * 32 + mt * 16 + (lane & 15);
            int c = k0 + ((lane >> 4) << 3);
            uint32_t addr = sA_base + (uint32_t)(r * SH_STRIDE + c) * 2;
            LDSM_X4(a[mt][0], a[mt][1], a[mt][2], a[mt][3], addr);
        }
        // B fragments: x4 covers two n8-frags (n, n+8)
        uint32_t b[4][4];
#pragma unroll
        for (int p = 0; p < 4; p++) {
            int n = wn * 64 + p * 16 + ((lane >= 16) ? 8 : 0) + (lane & 7);
            int c = k0 + (((lane >> 3) & 1) << 3);
            uint32_t addr = sW_base + (uint32_t)(n * SH_STRIDE + c) * 2;
            LDSM_X4(b[p][0], b[p][1], b[p][2], b[p][3], addr);
        }
#pragma unroll
        for (int nt = 0; nt < 8; nt++) {
            uint32_t b0 = b[nt >> 1][(nt & 1) ? 2 : 0];
            uint32_t b1 = b[nt >> 1][(nt & 1) ? 3 : 1];
#pragma unroll
            for (int mt = 0; mt < 2; mt++) {
                asm volatile(
                    "mma.sync.aligned.m16n8k16.row.col.f32.f16.f16.f32 "
                    "{%0,%1,%2,%3}, {%4,%5,%6,%7}, {%8,%9}, {%0,%1,%2,%3};"
                    : "+f"(acc[mt][nt][0]), "+f"(acc[mt][nt][1]),
                      "+f"(acc[mt][nt][2]), "+f"(acc[mt][nt][3])
                    : "r"(a[mt][0]), "r"(a[mt][1]),
                      "r"(a[mt][2]), "r"(a[mt][3]),
                      "r"(b0), "r"(b1));
            }
        }
    }

    // ---- epilogue: bias + store ----
#pragma unroll
    for (int mt = 0; mt < 2; mt++) {
        int r0 = row0 + wm * 32 + mt * 16 + (lane >> 2);
        int r1 = r0 + 8;
#pragma unroll
        for (int nt = 0; nt < 8; nt++) {
            int c = wn * 64 + nt * 8 + (lane & 3) * 2;
            float2 bb = __ldg((const float2*)&bias[c]);
            if (r0 < N_NODES) {
                float2 o = make_float2(acc[mt][nt][0] + bb.x,
                                       acc[mt][nt][1] + bb.y);
                *(float2*)&out[(size_t)r0 * DIM + c] = o;
            }
            if (r1 < N_NODES) {
                float2 o = make_float2(acc[mt][nt][2] + bb.x,
                                       acc[mt][nt][3] + bb.y);
                *(float2*)&out[(size_t)r1 * DIM + c] = o;
            }
        }
    }
}

// ---------------------------------------------------------------------------
// Launch
// ---------------------------------------------------------------------------
extern "C" void kernel_launch(void* const* d_in, const int* in_sizes, int n_in,
                              void* d_out, int out_size) {
    const float* h        = (const float*)d_in[0];
    const float* W        = (const float*)d_in[1];
    const float* b        = (const float*)d_in[2];
    const int*   edge_src = (const int*)d_in[3];
    const int*   edge_dst = (const int*)d_in[4];
    float*       out      = (float*)d_out;

    zero_deg_kernel<<<(N_NODES + 255) / 256, 256>>>();
    deg_kernel<<<(N_EDGES + 255) / 256, 256>>>(edge_dst);
    scan_block_kernel<<<NSCAN, SCAN_BS>>>();
    finalize_kernel<<<(N_NODES + 255) / 256, 256>>>();
    csr_scatter_kernel<<<(N_EDGES + 255) / 256, 256>>>(edge_src, edge_dst);
    cvt_h_kernel<<<(N_NODES * DIM / 8 + 255) / 256, 256>>>(h);

    {   // one warp per node
        int blocks = (N_NODES + 7) / 8;
        gather_kernel<<<blocks, 256>>>();
    }

    (void)cudaFuncSetAttribute(mma_gemm_kernel,
                               cudaFuncAttributeMaxDynamicSharedMemorySize,
                               SMEM_SZ);
    int tiles = (N_NODES + 127) / 128;   // 782
    mma_gemm_kernel<<<tiles, 256, SMEM_SZ>>>(W, b, out);
}

// round 13
// speedup vs baseline: 1.6902x; 1.0557x over previous
#include <cuda_runtime.h>
#include <cuda_fp16.h>
#include <cstdint>

#define N_NODES 100000
#define N_EDGES 1600000
#define DIM     128
#define SCAN_BS 1024
#define NSCAN   ((N_NODES + SCAN_BS - 1) / SCAN_BS)   // 98

#define SCAT_BLOCKS ((N_EDGES + 255) / 256)           // 6250
#define CVT_BLOCKS  ((N_NODES * DIM / 8 + 255) / 256) // 6250

// Scratch (no cudaMalloc allowed)
__device__ __half   g_agg16[(size_t)N_NODES * DIM];  // fp16 normalized aggregate
__device__ __half   g_h16[(size_t)N_NODES * DIM];    // fp16 h prescaled by norm[row]
__device__ int      g_deg[N_NODES];
__device__ float    g_norm[N_NODES];
__device__ int      g_part[N_NODES];
__device__ int      g_bsum[NSCAN];
__device__ int      g_row_start[N_NODES + 1];
__device__ int      g_cursor[N_NODES];
__device__ int      g_sorted_src[N_EDGES];

// ---------------------------------------------------------------------------
// 1. zero degree counters
// ---------------------------------------------------------------------------
__global__ void zero_deg_kernel() {
    int i = blockIdx.x * blockDim.x + threadIdx.x;
    if (i < N_NODES) g_deg[i] = 0;
}

// ---------------------------------------------------------------------------
// 2. in-degree histogram
// ---------------------------------------------------------------------------
__global__ void deg_kernel(const int* __restrict__ edge_dst) {
    int i = blockIdx.x * blockDim.x + threadIdx.x;
    if (i < N_EDGES) atomicAdd(&g_deg[edge_dst[i]], 1);
}

// ---------------------------------------------------------------------------
// 3a. per-block exclusive scan of deg
// ---------------------------------------------------------------------------
__global__ __launch_bounds__(SCAN_BS)
void scan_block_kernel() {
    __shared__ int s[SCAN_BS];
    int tid = threadIdx.x;
    int gi  = blockIdx.x * SCAN_BS + tid;
    int v = (gi < N_NODES) ? g_deg[gi] : 0;
    s[tid] = v;
    __syncthreads();
#pragma unroll
    for (int off = 1; off < SCAN_BS; off <<= 1) {
        int t = (tid >= off) ? s[tid - off] : 0;
        __syncthreads();
        s[tid] += t;
        __syncthreads();
    }
    if (gi < N_NODES) g_part[gi] = s[tid] - v;
    if (tid == SCAN_BS - 1) g_bsum[blockIdx.x] = s[tid];
}

// ---------------------------------------------------------------------------
// 3b. finalize: re-scan block sums locally, build row_start/cursor/norm
// ---------------------------------------------------------------------------
__global__ __launch_bounds__(256)
void finalize_kernel() {
    __shared__ int ss[128];
    int tid = threadIdx.x;
    if (tid < 128) ss[tid] = (tid < NSCAN) ? g_bsum[tid] : 0;
    __syncthreads();
#pragma unroll
    for (int off = 1; off < 128; off <<= 1) {
        int t = (tid < 128 && tid >= off) ? ss[tid - off] : 0;
        __syncthreads();
        if (tid < 128) ss[tid] += t;
        __syncthreads();
    }
    int i = blockIdx.x * blockDim.x + tid;
    if (i < N_NODES) {
        int reg = i / SCAN_BS;
        int boff = (reg == 0) ? 0 : ss[reg - 1];
        int rs = g_part[i] + boff;
        g_row_start[i] = rs;
        g_cursor[i]    = rs;
        int d = g_deg[i];
        g_norm[i] = rsqrtf((float)(d > 0 ? d : 1));
    }
    if (i == 0) g_row_start[N_NODES] = N_EDGES;
}

// ---------------------------------------------------------------------------
// 4. FUSED: edge bucketing (blocks [0, SCAT_BLOCKS)) +
//           h -> prescaled fp16 conversion (blocks [SCAT_BLOCKS, ...))
//    Both depend only on finalize; disjoint resources -> overlap.
// ---------------------------------------------------------------------------
__global__ __launch_bounds__(256)
void scatter_cvt_kernel(const float* __restrict__ h,
                        const int*   __restrict__ edge_src,
                        const int*   __restrict__ edge_dst) {
    int b = blockIdx.x;
    if (b < SCAT_BLOCKS) {
        int e = b * 256 + threadIdx.x;
        if (e < N_EDGES) {
            int d = edge_dst[e];
            int pos = atomicAdd(&g_cursor[d], 1);
            g_sorted_src[pos] = edge_src[e];
        }
    } else {
        int i = (b - SCAT_BLOCKS) * 256 + threadIdx.x;   // over N*DIM/8
        if (i < N_NODES * DIM / 8) {
            float nr = __ldg(&g_norm[i >> 4]);
            const float4* h4 = (const float4*)h;
            float4 a = __ldg(&h4[i * 2]);
            float4 bb = __ldg(&h4[i * 2 + 1]);
            __half2 p0 = __floats2half2_rn(a.x * nr, a.y * nr);
            __half2 p1 = __floats2half2_rn(a.z * nr, a.w * nr);
            __half2 p2 = __floats2half2_rn(bb.x * nr, bb.y * nr);
            __half2 p3 = __floats2half2_rn(bb.z * nr, bb.w * nr);
            uint4 o;
            o.x = *(uint32_t*)&p0; o.y = *(uint32_t*)&p1;
            o.z = *(uint32_t*)&p2; o.w = *(uint32_t*)&p3;
            ((uint4*)g_h16)[i] = o;
        }
    }
}

// ---------------------------------------------------------------------------
// 5. gather-aggregate: one warp per node, fp32 acc, fp16 store.
//    Unroll 8 + tail 4 + singles.
// ---------------------------------------------------------------------------
__global__ __launch_bounds__(256)
void gather_kernel() {
    int warp = (blockIdx.x * blockDim.x + threadIdx.x) >> 5;
    int lane = threadIdx.x & 31;
    if (warp >= N_NODES) return;

    int start = __ldg(&g_row_start[warp]);
    int end   = __ldg(&g_row_start[warp + 1]);

    const uint2* h2 = (const uint2*)g_h16;   // 32 uint2 per row
    float4 acc = make_float4(0.f, 0.f, 0.f, 0.f);

    int e = start;
    for (; e + 7 < end; e += 8) {
        int s[8];
#pragma unroll
        for (int j = 0; j < 8; j++) s[j] = __ldg(&g_sorted_src[e + j]);
        uint2 u[8];
#pragma unroll
        for (int j = 0; j < 8; j++) u[j] = __ldg(&h2[(size_t)s[j] * 32 + lane]);
#pragma unroll
        for (int j = 0; j < 8; j++) {
            float2 a = __half22float2(*(__half2*)&u[j].x);
            float2 b = __half22float2(*(__half2*)&u[j].y);
            acc.x += a.x; acc.y += a.y;
            acc.z += b.x; acc.w += b.y;
        }
    }
    if (e + 3 < end) {
        int s[4];
#pragma unroll
        for (int j = 0; j < 4; j++) s[j] = __ldg(&g_sorted_src[e + j]);
        uint2 u[4];
#pragma unroll
        for (int j = 0; j < 4; j++) u[j] = __ldg(&h2[(size_t)s[j] * 32 + lane]);
#pragma unroll
        for (int j = 0; j < 4; j++) {
            float2 a = __half22float2(*(__half2*)&u[j].x);
            float2 b = __half22float2(*(__half2*)&u[j].y);
            acc.x += a.x; acc.y += a.y;
            acc.z += b.x; acc.w += b.y;
        }
        e += 4;
    }
    for (; e < end; e++) {
        int s0 = __ldg(&g_sorted_src[e]);
        uint2 u0 = __ldg(&h2[(size_t)s0 * 32 + lane]);
        float2 a0 = __half22float2(*(__half2*)&u0.x);
        float2 b0 = __half22float2(*(__half2*)&u0.y);
        acc.x += a0.x; acc.y += a0.y;
        acc.z += b0.x; acc.w += b0.y;
    }

    float nd = __ldg(&g_norm[warp]);
    __half2 p0 = __floats2half2_rn(acc.x * nd, acc.y * nd);
    __half2 p1 = __floats2half2_rn(acc.z * nd, acc.w * nd);
    uint2 o;
    o.x = *(uint32_t*)&p0;
    o.y = *(uint32_t*)&p1;
    ((uint2*)g_agg16)[(size_t)warp * 32 + lane] = o;
}

// ---------------------------------------------------------------------------
// 6. fp16 ldmatrix MMA GEMM: out = aggn @ W^T + b
//    m16n8k16, fp32 acc. 8 warps: 4m x 2n, warp tile 32x64.
// ---------------------------------------------------------------------------
#define SH_STRIDE 136
#define SMEM_HALF_W (128 * SH_STRIDE)                 // halves
#define SMEM_SZ (2 * SMEM_HALF_W * 2)                 // 69632 B

#define LDSM_X4(r0, r1, r2, r3, addr) \
    asm volatile("ldmatrix.sync.aligned.m8n8.x4.shared.b16 {%0,%1,%2,%3}, [%4];" \
        : "=r"(r0), "=r"(r1), "=r"(r2), "=r"(r3) : "r"(addr))

__global__ __launch_bounds__(256)
void mma_gemm_kernel(const float* __restrict__ W,
                     const float* __restrict__ bias,
                     float*       __restrict__ out) {
    extern __shared__ __half smh[];
    __half* sW = smh;                    // [n][k]
    __half* sA = smh + SMEM_HALF_W;      // [m][k]

    int tid  = threadIdx.x;
    int lane = tid & 31;
    int warp = tid >> 5;
    int wm   = warp & 3;      // m0 = wm*32
    int wn   = warp >> 2;     // n0 = wn*64
    int row0 = blockIdx.x * 128;

    // ---- stage W as fp16 ----
    {
        const float4* W4 = (const float4*)W;
#pragma unroll
        for (int t = tid; t < 4096; t += 256) {
            int n = t >> 5;
            int q = t & 31;
            float4 w = __ldg(&W4[n * 32 + q]);
            __half2 h0 = __floats2half2_rn(w.x, w.y);
            __half2 h1 = __floats2half2_rn(w.z, w.w);
            uint32_t* p = (uint32_t*)&sW[n * SH_STRIDE + q * 4];
            p[0] = *(uint32_t*)&h0;
            p[1] = *(uint32_t*)&h1;
        }
    }
    // ---- stage A (fp16 bit-copy) ----
    {
        const uint2* A2 = (const uint2*)g_agg16;
#pragma unroll
        for (int t = tid; t < 4096; t += 256) {
            int m = t >> 5;
            int q = t & 31;
            int row = row0 + m;
            uint2 a = make_uint2(0u, 0u);
            if (row < N_NODES) a = __ldg(&A2[(size_t)row * 32 + q]);
            uint32_t* p = (uint32_t*)&sA[m * SH_STRIDE + q * 4];
            p[0] = a.x;
            p[1] = a.y;
        }
    }
    __syncthreads();

    float acc[2][8][4];
#pragma unroll
    for (int mt = 0; mt < 2; mt++)
#pragma unroll
        for (int nt = 0; nt < 8; nt++)
#pragma unroll
            for (int c = 0; c < 4; c++) acc[mt][nt][c] = 0.f;

    uint32_t sA_base = (uint32_t)__cvta_generic_to_shared(sA);
    uint32_t sW_base = (uint32_t)__cvta_generic_to_shared(sW);

#pragma unroll
    for (int ks = 0; ks < 8; ks++) {
        int k0 = ks * 16;
        uint32_t a[2][4];
#pragma unroll
        for (int mt = 0; mt < 2; mt++) {
            int r = wm * 32 + mt * 16 + (lane & 15);
            int c = k0 + ((lane >> 4) << 3);
            uint32_t addr = sA_base + (uint32_t)(r * SH_STRIDE + c) * 2;
            LDSM_X4(a[mt][0], a[mt][1], a[mt][2], a[mt][3], addr);
        }
        uint32_t b[4][4];
#pragma unroll
        for (int p = 0; p < 4; p++) {
            int n = wn * 64 + p * 16 + ((lane >= 16) ? 8 : 0) + (lane & 7);
            int c = k0 + (((lane >> 3) & 1) << 3);
            uint32_t addr = sW_base + (uint32_t)(n * SH_STRIDE + c) * 2;
            LDSM_X4(b[p][0], b[p][1], b[p][2], b[p][3], addr);
        }
#pragma unroll
        for (int nt = 0; nt < 8; nt++) {
            uint32_t b0 = b[nt >> 1][(nt & 1) ? 2 : 0];
            uint32_t b1 = b[nt >> 1][(nt & 1) ? 3 : 1];
#pragma unroll
            for (int mt = 0; mt < 2; mt++) {
                asm volatile(
                    "mma.sync.aligned.m16n8k16.row.col.f32.f16.f16.f32 "
                    "{%0,%1,%2,%3}, {%4,%5,%6,%7}, {%8,%9}, {%0,%1,%2,%3};"
                    : "+f"(acc[mt][nt][0]), "+f"(acc[mt][nt][1]),
                      "+f"(acc[mt][nt][2]), "+f"(acc[mt][nt][3])
                    : "r"(a[mt][0]), "r"(a[mt][1]),
                      "r"(a[mt][2]), "r"(a[mt][3]),
                      "r"(b0), "r"(b1));
            }
        }
    }

    // ---- epilogue: bias + store ----
#pragma unroll
    for (int mt = 0; mt < 2; mt++) {
        int r0 = row0 + wm * 32 + mt * 16 + (lane >> 2);
        int r1 = r0 + 8;
#pragma unroll
        for (int nt = 0; nt < 8; nt++) {
            int c = wn * 64 + nt * 8 + (lane & 3) * 2;
            float2 bb = __ldg((const float2*)&bias[c]);
            if (r0 < N_NODES) {
                float2 o = make_float2(acc[mt][nt][0] + bb.x,
                                       acc[mt][nt][1] + bb.y);
                *(float2*)&out[(size_t)r0 * DIM + c] = o;
            }
            if (r1 < N_NODES) {
                float2 o = make_float2(acc[mt][nt][2] + bb.x,
                                       acc[mt][nt][3] + bb.y);
                *(float2*)&out[(size_t)r1 * DIM + c] = o;
            }
        }
    }
}

// ---------------------------------------------------------------------------
// Launch
// ---------------------------------------------------------------------------
extern "C" void kernel_launch(void* const* d_in, const int* in_sizes, int n_in,
                              void* d_out, int out_size) {
    const float* h        = (const float*)d_in[0];
    const float* W        = (const float*)d_in[1];
    const float* b        = (const float*)d_in[2];
    const int*   edge_src = (const int*)d_in[3];
    const int*   edge_dst = (const int*)d_in[4];
    float*       out      = (float*)d_out;

    zero_deg_kernel<<<(N_NODES + 255) / 256, 256>>>();
    deg_kernel<<<(N_EDGES + 255) / 256, 256>>>(edge_dst);
    scan_block_kernel<<<NSCAN, SCAN_BS>>>();
    finalize_kernel<<<(N_NODES + 255) / 256, 256>>>();
    scatter_cvt_kernel<<<SCAT_BLOCKS + CVT_BLOCKS, 256>>>(h, edge_src, edge_dst);

    {   // one warp per node
        int blocks = (N_NODES + 7) / 8;
        gather_kernel<<<blocks, 256>>>();
    }

    (void)cudaFuncSetAttribute(mma_gemm_kernel,
                               cudaFuncAttributeMaxDynamicSharedMemorySize,
                               SMEM_SZ);
    int tiles = (N_NODES + 127) / 128;   // 782
    mma_gemm_kernel<<<tiles, 256, SMEM_SZ>>>(W, b, out);
}